// round 9
// baseline (speedup 1.0000x reference)
#include <cuda_runtime.h>
#include <cstdint>

#define Bsz    32
#define C_INc  128
#define Lseq   4096
#define C_OUTc 256
#define PKw    9
#define PADw   4

#define M_TILE 128     // l positions per CTA
#define NCH    36      // K chunks: 9 taps x 4 c-subchunks of 32

// k-pair permutation within groups of 8: logical c -> stored position,
// so fragment pairs (k, k+4) are adjacent -> LDS.64
#define PERMC(c) (((c) & ~7) + (((c) & 3) << 1) + (((c) >> 2) & 1))

// __device__ globals: sanctioned scratch (no cudaMalloc allowed)
__device__ float g_saT[(size_t)Bsz * Lseq * C_INc];    // [b][l][perm(c)], tf32
__device__ float g_wB [(size_t)PKw * C_OUTc * C_INc];  // [kk][o][perm(c)], tf32

// ---------------------------------------------------------------------------
__device__ __forceinline__ uint32_t smem_u32(const void* p) {
    uint32_t a;
    asm("{ .reg .u64 t; cvta.to.shared.u64 t, %1; cvt.u32.u64 %0, t; }" : "=r"(a) : "l"(p));
    return a;
}
__device__ __forceinline__ uint32_t f2tf32(float x) {
    uint32_t u; asm("cvt.rn.tf32.f32 %0, %1;" : "=r"(u) : "f"(x)); return u;
}
__device__ __forceinline__ float selu_f(float x) {
    return 1.0507009873554805f * (x > 0.f ? x : 1.6732632423543772f * expm1f(x));
}
__device__ __forceinline__ void cp16(uint32_t dst, const float* src) {
    asm volatile("{ .reg .u64 g; cvta.to.global.u64 g, %1;"
                 "  cp.async.ca.shared.global [%0], [g], 16; }"
                 :: "r"(dst), "l"(src) : "memory");
}
__device__ __forceinline__ void mma_tf32(float* c, const uint32_t* a, const uint32_t* b) {
    asm volatile(
        "mma.sync.aligned.m16n8k8.row.col.f32.tf32.tf32.f32 "
        "{%0,%1,%2,%3}, {%4,%5,%6,%7}, {%8,%9}, {%0,%1,%2,%3};"
        : "+f"(c[0]), "+f"(c[1]), "+f"(c[2]), "+f"(c[3])
        : "r"(a[0]), "r"(a[1]), "r"(a[2]), "r"(a[3]), "r"(b[0]), "r"(b[1]));
}

// ---------------------------------------------------------------------------
// Weight prep: g_wB[kk][o][perm(c)] = tf32_rn(of[o][c][kk])
// ---------------------------------------------------------------------------
__global__ void k_wprep(const float* __restrict__ of) {
    int idx = blockIdx.x * 256 + threadIdx.x;         // enumerate [kk][o][c]
    if (idx < PKw * C_OUTc * C_INc) {
        int c   = idx & 127;
        int t   = idx >> 7;
        int o   = t & 255;
        int kk  = t >> 8;
        ((uint32_t*)g_wB)[(t << 7) + PERMC(c)] = f2tf32(of[(o * C_INc + c) * PKw + kk]);
    }
}

// ---------------------------------------------------------------------------
// Stage 1: per-patch depthwise conv -> g_saT[b][l][perm(c)] (tf32-rounded)
// Block: (l-tile 128 = 2 patches, b). 128 threads, c in chunks of 32.
// ---------------------------------------------------------------------------
__global__ __launch_bounds__(128) void k_stage1(const float* __restrict__ x,
                                                const float* __restrict__ pf) {
    __shared__ float x_s[32][132];       // [c][l]
    __shared__ uint32_t sa_s[128][36];   // [l][perm-c] tf32 bits
    __shared__ float pfs[32][2][PKw];

    const int l0 = blockIdx.x * 128;
    const int b  = blockIdx.y;
    const int tx = threadIdx.x;          // = l within tile
    const int p0 = l0 >> 6;

    for (int cb = 0; cb < C_INc; cb += 32) {
        for (int it = 0; it < 8; ++it) {
            int i = tx + (it << 7);              // 0..1023 float4s
            int c = i >> 5, seg = i & 31;
            *reinterpret_cast<float4*>(&x_s[c][seg * 4]) =
                *reinterpret_cast<const float4*>(&x[((size_t)(b * C_INc + cb + c)) * Lseq + l0 + seg * 4]);
        }
        for (int i = tx; i < 32 * 2 * PKw; i += 128) {
            int c = i / (2 * PKw), r = i % (2 * PKw);
            int p = r / PKw, k = r % PKw;
            pfs[c][p][k] = pf[((size_t)(cb + c) * 64 + p0 + p) * PKw + k];
        }
        __syncthreads();

        const int l  = tx;
        const int u  = l & 63;
        const int pl = l >> 6;
        #pragma unroll 4
        for (int c = 0; c < 32; ++c) {
            float acc = 0.f;
            #pragma unroll
            for (int k = 0; k < PKw; ++k) {
                int v = u + k - PADw;
                if ((unsigned)v < 64u)
                    acc = fmaf(x_s[c][l + k - PADw], pfs[c][pl][k], acc);
            }
            sa_s[l][PERMC(c)] = f2tf32(acc);
        }
        __syncthreads();

        for (int it = 0; it < 8; ++it) {
            int i = tx + (it << 7);              // 0..1023
            int row = i >> 3, seg = i & 7;
            float4 v = *reinterpret_cast<const float4*>(&sa_s[row][seg * 4]);
            *reinterpret_cast<float4*>(&g_saT[((size_t)b * Lseq + l0 + row) * C_INc + cb + seg * 4]) = v;
        }
        __syncthreads();
    }
}

// ---------------------------------------------------------------------------
// Stage 2: tf32 mma.sync implicit GEMM + fused SELU.
// CTA: 128 l x 256 o (ALL of C_OUT), 256 threads = 8 warps (2m x 4n),
// warp tile 64x64 (mt=4, nt=8). Fragment pairs via LDS.64 (perm layout).
// A resident in smem (tap shift kk = row offset); B double-buffered cp.async.
// ---------------------------------------------------------------------------
#define A_STRIDE 136                          // floats; 136 % 32 == 8 (conflict-free)
#define A_ROWS   136
#define A_BYTES  (A_ROWS * A_STRIDE * 4)      // 73984
#define W_STRIDE 40                           // floats; 40 % 32 == 8
#define W_BYTES  (256 * W_STRIDE * 4)         // 40960
#define OFF_W0   A_BYTES
#define OFF_W1   (A_BYTES + W_BYTES)
#define SMEM_SZ  (A_BYTES + 2 * W_BYTES)      // 155904
#define O_STRIDE 132                          // epilogue transpose stride

__device__ __forceinline__ void load_w_chunk(uint32_t sbase, int tid, int ch, int buf) {
    const int kk = ch >> 2, c0 = (ch & 3) << 5;
    const float* src = &g_wB[((size_t)kk << 15) + c0];
    const uint32_t dbase = sbase + (buf ? OFF_W1 : OFF_W0);
    #pragma unroll
    for (int it = 0; it < 8; ++it) {
        int i = tid + (it << 8);               // 0..2047 16B transfers
        int o = i >> 3, s = i & 7;
        cp16(dbase + (uint32_t)(o * W_STRIDE + s * 4) * 4,
             src + ((size_t)o << 7) + s * 4);
    }
    asm volatile("cp.async.commit_group;" ::: "memory");
}

__global__ __launch_bounds__(256, 1) void k_stage2(float* __restrict__ out) {
    extern __shared__ __align__(16) char smem[];
    float* a_s = reinterpret_cast<float*>(smem);
    const uint32_t sbase = smem_u32(smem);

    const int l0 = blockIdx.x * M_TILE;
    const int b  = blockIdx.y;
    const int tid  = threadIdx.x;
    const int lane = tid & 31, wid = tid >> 5;
    const int wm = wid & 1;        // m half (64 rows)
    const int wn = wid >> 1;       // n quarter (64 cols)

    // ---- stage A: rows l0-4 .. l0+131 of g_saT[b][.][perm-c], zero-filled OOB
    for (int it = 0; it < 17; ++it) {
        int i = tid + (it << 8);               // 0..4351
        int row = i >> 5, c4 = i & 31;
        int gl = l0 - PADw + row;
        float4 v = make_float4(0.f, 0.f, 0.f, 0.f);
        if ((unsigned)gl < (unsigned)Lseq)
            v = *reinterpret_cast<const float4*>(&g_saT[((size_t)b * Lseq + gl) * C_INc + c4 * 4]);
        *reinterpret_cast<float4*>(&a_s[row * A_STRIDE + c4 * 4]) = v;
    }

    float acc[4][8][4];
    #pragma unroll
    for (int mt = 0; mt < 4; ++mt)
        #pragma unroll
        for (int nt = 0; nt < 8; ++nt)
            #pragma unroll
            for (int r = 0; r < 4; ++r) acc[mt][nt][r] = 0.f;

    const uint32_t* au = reinterpret_cast<const uint32_t*>(a_s);
    const int jj = (lane & 3) << 1;
    const int obase = wn * 64 + (lane >> 2);

    load_w_chunk(sbase, tid, 0, 0);
    for (int ch = 0; ch < NCH; ++ch) {
        const int buf = ch & 1;
        if (ch + 1 < NCH) {
            load_w_chunk(sbase, tid, ch + 1, buf ^ 1);
            asm volatile("cp.async.wait_group 1;" ::: "memory");
        } else {
            asm volatile("cp.async.wait_group 0;" ::: "memory");
        }
        __syncthreads();

        const int kk = ch >> 2, c0 = (ch & 3) << 5;
        const uint32_t* wu = reinterpret_cast<const uint32_t*>(smem + (buf ? OFF_W1 : OFF_W0));
        const int rbase = wm * 64 + (lane >> 2) + kk;   // +4 halo baked into row index

        #pragma unroll
        for (int kb = 0; kb < 4; ++kb) {
            const int acol = c0 + kb * 8 + jj;
            uint32_t a[4][4];
            #pragma unroll
            for (int mt = 0; mt < 4; ++mt) {
                int r = rbase + mt * 16;
                uint2 lo = *reinterpret_cast<const uint2*>(&au[r * A_STRIDE + acol]);
                uint2 hi = *reinterpret_cast<const uint2*>(&au[(r + 8) * A_STRIDE + acol]);
                a[mt][0] = lo.x; a[mt][2] = lo.y;
                a[mt][1] = hi.x; a[mt][3] = hi.y;
            }
            uint32_t bb[8][2];
            #pragma unroll
            for (int nt = 0; nt < 8; ++nt) {
                uint2 w = *reinterpret_cast<const uint2*>(&wu[(obase + nt * 8) * W_STRIDE + kb * 8 + jj]);
                bb[nt][0] = w.x; bb[nt][1] = w.y;
            }
            #pragma unroll
            for (int mt = 0; mt < 4; ++mt)
                #pragma unroll
                for (int nt = 0; nt < 8; ++nt)
                    mma_tf32(acc[mt][nt], a[mt], bb[nt]);
        }
        __syncthreads();
    }

    // ---- epilogue: transpose through smem -> coalesced SELU stores
    float* o_s = a_s;                          // [256 o][132 l] = 135168 B <= SMEM_SZ
    #pragma unroll
    for (int mt = 0; mt < 4; ++mt)
        #pragma unroll
        for (int nt = 0; nt < 8; ++nt) {
            int m = wm * 64 + mt * 16 + (lane >> 2);
            int o = wn * 64 + nt * 8 + 2 * (lane & 3);
            o_s[o * O_STRIDE + m]           = acc[mt][nt][0];
            o_s[(o + 1) * O_STRIDE + m]     = acc[mt][nt][1];
            o_s[o * O_STRIDE + m + 8]       = acc[mt][nt][2];
            o_s[(o + 1) * O_STRIDE + m + 8] = acc[mt][nt][3];
        }
    __syncthreads();

    for (int it = 0; it < 32; ++it) {
        int i = tid + (it << 8);               // 0..8191 float4s
        int ol = i >> 5, s = i & 31;
        float4 v = *reinterpret_cast<const float4*>(&o_s[ol * O_STRIDE + s * 4]);
        v.x = selu_f(v.x); v.y = selu_f(v.y); v.z = selu_f(v.z); v.w = selu_f(v.w);
        *reinterpret_cast<float4*>(&out[((size_t)(b * C_OUTc + ol)) * Lseq + l0 + s * 4]) = v;
    }
}

// ---------------------------------------------------------------------------
extern "C" void kernel_launch(void* const* d_in, const int* in_sizes, int n_in,
                              void* d_out, int out_size) {
    (void)in_sizes; (void)n_in; (void)out_size;
    const float* x  = (const float*)d_in[0];   // (32,128,4096)
    const float* pf = (const float*)d_in[1];   // (128,64,1,9)
    const float* of = (const float*)d_in[2];   // (256,128,9)
    float* out = (float*)d_out;                // (32,256,4096)

    cudaFuncSetAttribute(k_stage2, cudaFuncAttributeMaxDynamicSharedMemorySize, SMEM_SZ);

    k_wprep<<<(PKw * C_OUTc * C_INc + 255) / 256, 256>>>(of);
    k_stage1<<<dim3(Lseq / 128, Bsz), 128>>>(x, pf);
    k_stage2<<<dim3(Lseq / M_TILE, Bsz), 256, SMEM_SZ>>>(out);
}